// round 11
// baseline (speedup 1.0000x reference)
#include <cuda_runtime.h>
#include <cstdint>

#define NN    65536      // total nodes = B*C*NMAX
#define HID   128
#define NE    1048576    // edges
#define KDEC  256        // NMAX (decode GEMM K)
#define BATCH 256

#define WS_STRIDE 136    // W smem row stride (floats): B-frag reads conflict-free
#define AS_STRIDE 36     // A smem row stride (floats): A-frag reads conflict-free
#define KW        128    // W chunk rows resident in smem

// one smem layout for all GEMMs: Ws[128][136] + As[2][128][36]
#define SMEM_WS_FLOATS (KW * WS_STRIDE)
#define SMEM_AS_FLOATS (2 * 128 * AS_STRIDE)
#define SMEM_GEMM_B    ((SMEM_WS_FLOATS + SMEM_AS_FLOATS) * 4)   // 106,496 B

// ---------------- scratch (device globals; no allocation allowed) ----------
__device__ float g_x[NN * HID];     // 32 MB
__device__ float g_h[NN * HID];     // 32 MB
__device__ float g_y[NN * HID];     // 32 MB
__device__ int   g_deg[NN];
__device__ float g_dinv[NN];
__device__ int   g_bsum[256];
__device__ int   g_boff[256];
__device__ int   g_off[NN];
__device__ int   g_cur[NN];
__device__ int   g_esrc[NE];
__device__ float g_ecoef[NE];

// cvt.*.tf32.f32 requires a .b32 destination register -> "=r" constraint.
__device__ __forceinline__ uint32_t to_tf32(float x) {
    uint32_t r;
    asm("cvt.rna.tf32.f32 %0, %1;" : "=r"(r) : "f"(x));
    return r;
}
__device__ __forceinline__ float to_tf32f(float x) {
    return __uint_as_float(to_tf32(x));
}
__device__ __forceinline__ uint32_t smem_u32(const void* p) {
    uint32_t a;
    asm("{ .reg .u64 t; cvta.to.shared.u64 t, %1; cvt.u32.u64 %0, t; }"
        : "=r"(a) : "l"(p));
    return a;
}
#define CP_ASYNC16(saddr, gptr) \
    asm volatile("cp.async.cg.shared.global [%0], [%1], 16;" \
                 :: "r"(saddr), "l"(gptr))
#define CP_COMMIT() asm volatile("cp.async.commit_group;" ::: "memory")
#define CP_WAIT0()  asm volatile("cp.async.wait_group 0;" ::: "memory")

// ---------------- degree / CSR build --------------------------------------
__global__ void k_zero_deg() {
    g_deg[blockIdx.x * 256 + threadIdx.x] = 0;
}

__global__ void k_count(const int* __restrict__ edges) {
    int e = blockIdx.x * 256 + threadIdx.x;
    atomicAdd(&g_deg[edges[2 * e + 1]], 1);
}

__global__ void k_dinv() {
    int i = blockIdx.x * 256 + threadIdx.x;
    g_dinv[i] = rsqrtf((float)g_deg[i] + 1.0f);
}

__global__ void k_scan1() {
    __shared__ int s[256];
    int t = threadIdx.x;
    s[t] = g_deg[blockIdx.x * 256 + t];
    __syncthreads();
    for (int o = 128; o > 0; o >>= 1) {
        if (t < o) s[t] += s[t + o];
        __syncthreads();
    }
    if (t == 0) g_bsum[blockIdx.x] = s[0];
}

__global__ void k_scan2() {
    __shared__ int s[256];
    int t = threadIdx.x;
    int v = g_bsum[t];
    s[t] = v;
    __syncthreads();
    for (int o = 1; o < 256; o <<= 1) {
        int u = (t >= o) ? s[t - o] : 0;
        __syncthreads();
        s[t] += u;
        __syncthreads();
    }
    g_boff[t] = s[t] - v;
}

__global__ void k_scan3() {
    __shared__ int s[256];
    int t = threadIdx.x;
    int gi = blockIdx.x * 256 + t;
    int v = g_deg[gi];
    s[t] = v;
    __syncthreads();
    for (int o = 1; o < 256; o <<= 1) {
        int u = (t >= o) ? s[t - o] : 0;
        __syncthreads();
        s[t] += u;
        __syncthreads();
    }
    int excl = s[t] - v + g_boff[blockIdx.x];
    g_off[gi] = excl;
    g_cur[gi] = excl;
}

__global__ void k_fill(const int* __restrict__ edges) {
    int e = blockIdx.x * 256 + threadIdx.x;
    int src = edges[2 * e + 0];
    int dst = edges[2 * e + 1];
    int pos = atomicAdd(&g_cur[dst], 1);
    g_esrc[pos]  = src;
    g_ecoef[pos] = g_dinv[src] * g_dinv[dst];
}

// ---------------- tf32 tensor-core GEMM (legacy mma.sync, sm_80+) ----------
// C[M,128] = (relu? A)[M,K] @ W[K,128] (+bias)
// 256 threads = 8 warps (4x2); block tile 128x128; warp tile 32x64.
// K processed in 128-row W chunks (Ws re-staged per chunk, tf32 RN).
// A staged via cp.async, double-buffered; ONE barrier per chunk:
// the top-of-iteration wait+sync proves all warps finished mma(c-1),
// so cp.async into buffer c+1 (== buffer c-1) needs no trailing sync.
__device__ __forceinline__ void mma_tf32(float* d, uint32_t a0, uint32_t a1,
                                         uint32_t a2, uint32_t a3,
                                         uint32_t b0, uint32_t b1) {
    asm volatile(
        "mma.sync.aligned.m16n8k8.row.col.f32.tf32.tf32.f32 "
        "{%0,%1,%2,%3}, {%4,%5,%6,%7}, {%8,%9}, {%0,%1,%2,%3};"
        : "+f"(d[0]), "+f"(d[1]), "+f"(d[2]), "+f"(d[3])
        : "r"(a0), "r"(a1), "r"(a2), "r"(a3), "r"(b0), "r"(b1));
}

template<int K>
__global__ __launch_bounds__(256, 2)
void k_gemm_mma(const float* __restrict__ A, const float* __restrict__ W,
                const float* __restrict__ bias, float* __restrict__ C,
                int relu_in) {
    extern __shared__ float sm[];
    float* Ws = sm;                        // [KW][WS_STRIDE]
    float* As = sm + SMEM_WS_FLOATS;       // [2][128][AS_STRIDE]

    int tid  = threadIdx.x;
    int lane = tid & 31, wid = tid >> 5;
    int wr = wid >> 1, wc = wid & 1;       // warp row 0..3, warp col 0..1
    int g = lane >> 2, t = lane & 3;       // fragment coords

    const float* Ablk = A + (size_t)blockIdx.x * 128 * K;

    // this thread's A-chunk slots: 4x 16B covering 128x32 floats
    int arow[4], acol[4];
    uint32_t asaddr[2][4];
    uint32_t as_base = smem_u32(As);
#pragma unroll
    for (int it = 0; it < 4; it++) {
        int u = it * 256 + tid;
        arow[it] = u >> 3;
        acol[it] = (u & 7) * 4;
#pragma unroll
        for (int b = 0; b < 2; b++)
            asaddr[b][it] = as_base +
                (uint32_t)(b * 128 * AS_STRIDE + arow[it] * AS_STRIDE + acol[it]) * 4u;
    }

    float d[2][8][4];
#pragma unroll
    for (int mt = 0; mt < 2; mt++)
#pragma unroll
        for (int nt = 0; nt < 8; nt++)
#pragma unroll
            for (int j = 0; j < 4; j++) d[mt][nt][j] = 0.0f;

    for (int kw = 0; kw < K; kw += KW) {
        __syncthreads();                   // prior chunk's Ws/buffer reads done
        // stage W rows [kw, kw+128) (tf32 RN), conflict-free padded layout
        for (int u = tid; u < KW * 128; u += 256) {
            int k = u >> 7, n = u & 127;
            Ws[k * WS_STRIDE + n] = to_tf32f(W[(size_t)(kw + k) * 128 + n]);
        }
        // prefetch A chunk 0 of this kw into buffer 0
#pragma unroll
        for (int it = 0; it < 4; it++)
            CP_ASYNC16(asaddr[0][it],
                       &Ablk[(size_t)arow[it] * K + kw + acol[it]]);
        CP_COMMIT();

#pragma unroll
        for (int c = 0; c < 4; c++) {
            int buf = c & 1;
            CP_WAIT0();
            __syncthreads();               // chunk c data + Ws visible; all
                                           // warps past mma(c-1)

            if (c < 3) {                   // issue chunk c+1 during mma of c
                int k0n = kw + (c + 1) * 32;
#pragma unroll
                for (int it = 0; it < 4; it++)
                    CP_ASYNC16(asaddr[buf ^ 1][it],
                               &Ablk[(size_t)arow[it] * K + k0n + acol[it]]);
                CP_COMMIT();
            }

            const float* Ab = As + buf * 128 * AS_STRIDE;
#pragma unroll
            for (int kk = 0; kk < 4; kk++) {
                int kb   = kk * 8;
                int kabs = c * 32 + kb;    // row within this W chunk
                uint32_t b0[8], b1[8];
#pragma unroll
                for (int nt = 0; nt < 8; nt++) {
                    int col = wc * 64 + nt * 8 + g;
                    b0[nt] = __float_as_uint(Ws[(kabs + t)     * WS_STRIDE + col]);
                    b1[nt] = __float_as_uint(Ws[(kabs + t + 4) * WS_STRIDE + col]);
                }
#pragma unroll
                for (int mt = 0; mt < 2; mt++) {
                    int rb = wr * 32 + mt * 16;
                    float f0 = Ab[(rb + g)     * AS_STRIDE + kb + t];
                    float f1 = Ab[(rb + g + 8) * AS_STRIDE + kb + t];
                    float f2 = Ab[(rb + g)     * AS_STRIDE + kb + t + 4];
                    float f3 = Ab[(rb + g + 8) * AS_STRIDE + kb + t + 4];
                    if (relu_in) {
                        f0 = fmaxf(f0, 0.0f); f1 = fmaxf(f1, 0.0f);
                        f2 = fmaxf(f2, 0.0f); f3 = fmaxf(f3, 0.0f);
                    }
                    uint32_t a0 = to_tf32(f0), a1 = to_tf32(f1);
                    uint32_t a2 = to_tf32(f2), a3 = to_tf32(f3);
#pragma unroll
                    for (int nt = 0; nt < 8; nt++)
                        mma_tf32(d[mt][nt], a0, a1, a2, a3, b0[nt], b1[nt]);
                }
            }
            // no trailing sync: next iteration's wait+sync is the guard
        }
    }

    // epilogue: c0,c1 -> (row=g, col=2t,2t+1); c2,c3 -> row=g+8
    int blkrow = blockIdx.x * 128;
#pragma unroll
    for (int mt = 0; mt < 2; mt++) {
        int r0 = blkrow + wr * 32 + mt * 16 + g;
#pragma unroll
        for (int nt = 0; nt < 8; nt++) {
            int col = wc * 64 + nt * 8 + t * 2;
            float bx = 0.f, by = 0.f;
            if (bias) { bx = bias[col]; by = bias[col + 1]; }
            float2 v0 = make_float2(d[mt][nt][0] + bx, d[mt][nt][1] + by);
            float2 v1 = make_float2(d[mt][nt][2] + bx, d[mt][nt][3] + by);
            *(float2*)&C[(size_t)r0 * 128 + col]       = v0;
            *(float2*)&C[(size_t)(r0 + 8) * 128 + col] = v1;
        }
    }
}

// ---------------- GCN aggregate: warp per node, CSR gather ----------------
__global__ void k_gather(const float* __restrict__ h,
                         const float* __restrict__ bias,
                         float* __restrict__ out) {
    int v    = blockIdx.x * 8 + (threadIdx.x >> 5);
    int lane = threadIdx.x & 31;
    const float4* h4 = (const float4*)h;

    float dv   = g_dinv[v];
    int   base = g_off[v];
    int   cnt  = g_deg[v];

    float4 acc = make_float4(0.f, 0.f, 0.f, 0.f);
#pragma unroll 4
    for (int i = 0; i < cnt; i++) {
        int   s = __ldg(&g_esrc[base + i]);
        float c = __ldg(&g_ecoef[base + i]);
        float4 hs = __ldg(&h4[(size_t)s * 32 + lane]);
        acc.x += hs.x * c; acc.y += hs.y * c;
        acc.z += hs.z * c; acc.w += hs.w * c;
    }
    float  d2 = dv * dv;
    float4 hv = __ldg(&h4[(size_t)v * 32 + lane]);
    float4 b4 = *(const float4*)&bias[lane * 4];
    acc.x += hv.x * d2 + b4.x;
    acc.y += hv.y * d2 + b4.y;
    acc.z += hv.z * d2 + b4.z;
    acc.w += hv.w * d2 + b4.w;
    ((float4*)out)[(size_t)v * 32 + lane] = acc;
}

// ---------------- pooled max + MLP head -----------------------------------
__global__ void k_pool_mlp(const float* __restrict__ X,
                           const float* __restrict__ Wp1,
                           const float* __restrict__ bp1,
                           const float* __restrict__ Wp2,
                           const float* __restrict__ bp2,
                           float* __restrict__ out) {
    __shared__ float p[128];
    __shared__ float red[128];
    int b = blockIdx.x;
    int f = threadIdx.x;

    float m = -3.4e38f;
    const float* base = X + (size_t)b * 256 * 128 + f;
    for (int n = 0; n < 256; n++) m = fmaxf(m, base[n * 128]);
    p[f] = fmaxf(m, 0.0f);
    __syncthreads();

    float acc = bp1[f];
    for (int k = 0; k < 128; k++) acc += p[k] * Wp1[k * 128 + f];
    red[f] = fmaxf(acc, 0.0f) * Wp2[f];
    __syncthreads();
    for (int s = 64; s > 0; s >>= 1) {
        if (f < s) red[f] += red[f + s];
        __syncthreads();
    }
    if (f == 0) out[b] = red[0] + bp2[0];
}

// ---------------- launch ---------------------------------------------------
extern "C" void kernel_launch(void* const* d_in, const int* in_sizes, int n_in,
                              void* d_out, int out_size) {
    const float* adj  = (const float*)d_in[0];
    const int*   edges= (const int*)  d_in[1];
    // d_in[2] = subgraph_idx (contiguous 256-node segments)
    const float* Wdec = (const float*)d_in[3];
    const float* bdec = (const float*)d_in[4];
    const float* Wc1  = (const float*)d_in[5];
    const float* bc1  = (const float*)d_in[6];
    const float* Wc2  = (const float*)d_in[7];
    const float* bc2  = (const float*)d_in[8];
    const float* Wp1  = (const float*)d_in[9];
    const float* bp1  = (const float*)d_in[10];
    const float* Wp2  = (const float*)d_in[11];
    const float* bp2  = (const float*)d_in[12];
    float* out = (float*)d_out;

    float *px, *ph, *py;
    cudaGetSymbolAddress((void**)&px, g_x);
    cudaGetSymbolAddress((void**)&ph, g_h);
    cudaGetSymbolAddress((void**)&py, g_y);

    cudaFuncSetAttribute(k_gemm_mma<KDEC>,
                         cudaFuncAttributeMaxDynamicSharedMemorySize, SMEM_GEMM_B);
    cudaFuncSetAttribute(k_gemm_mma<HID>,
                         cudaFuncAttributeMaxDynamicSharedMemorySize, SMEM_GEMM_B);

    // Fork: decode GEMM is independent of the CSR build -> run it on a side
    // stream so the ~25us CSR chain hides under the ~59us GEMM. Streams and
    // events are created per call and deliberately NOT destroyed: kernel_launch
    // runs only for the correctness pass and the capture pass (replays execute
    // the graph), so at most two small host objects leak. Fall back to the
    // serial (known-good) path if anything fails.
    cudaStream_t s2 = 0;
    cudaEvent_t e0 = 0, e1 = 0;
    bool fork =
        cudaStreamCreateWithFlags(&s2, cudaStreamNonBlocking) == cudaSuccess &&
        cudaEventCreateWithFlags(&e0, cudaEventDisableTiming) == cudaSuccess &&
        cudaEventCreateWithFlags(&e1, cudaEventDisableTiming) == cudaSuccess;

    // CSR head (independent of decode)
    k_zero_deg<<<NN / 256, 256>>>();                                   // 0
    k_count   <<<NE / 256, 256>>>(edges);                              // 1
    k_dinv    <<<NN / 256, 256>>>();                                   // 2

    // decode: x = adj @ Wdec + bdec   (kernel launch index 3 for ncu)
    if (fork) {
        cudaEventRecord(e0, 0);
        cudaStreamWaitEvent(s2, e0, 0);
        k_gemm_mma<KDEC><<<NN / 128, 256, SMEM_GEMM_B, s2>>>(adj, Wdec, bdec,
                                                             px, 0);
        cudaEventRecord(e1, s2);
    } else {
        k_gemm_mma<KDEC><<<NN / 128, 256, SMEM_GEMM_B>>>(adj, Wdec, bdec,
                                                         px, 0);
    }

    // CSR tail (runs concurrently with decode when forked)
    k_scan1<<<256, 256>>>();
    k_scan2<<<1, 256>>>();
    k_scan3<<<256, 256>>>();
    k_fill <<<NE / 256, 256>>>(edges);

    if (fork) cudaStreamWaitEvent(0, e1, 0);   // join before conv1 reads g_x

    // conv1: h = x @ Wc1 ; y = aggregate(h) + h*dinv^2 + bc1
    k_gemm_mma<HID><<<NN / 128, 256, SMEM_GEMM_B>>>(px, Wc1, nullptr, ph, 0);
    k_gather  <<<NN / 8, 256>>>(ph, bc1, py);

    // conv2: h = relu(y) @ Wc2 ; x = aggregate(h) + h*dinv^2 + bc2
    k_gemm_mma<HID><<<NN / 128, 256, SMEM_GEMM_B>>>(py, Wc2, nullptr, ph, 1);
    k_gather  <<<NN / 8, 256>>>(ph, bc2, px);

    // pool (relu∘max) + MLP head
    k_pool_mlp<<<BATCH, 128>>>(px, Wp1, bp1, Wp2, bp2, out);
}

// round 14
// speedup vs baseline: 1.1144x; 1.1144x over previous
#include <cuda_runtime.h>
#include <cstdint>

#define NN    65536      // total nodes = B*C*NMAX
#define HID   128
#define NE    1048576    // edges
#define KDEC  256        // NMAX (decode GEMM K)
#define BATCH 256

#define WS_STRIDE 72     // W smem row stride (floats), 72%32=8 -> B-frag conflict-free
#define AS_STRIDE 36     // A smem row stride (floats), 36%32=4 -> A-frag conflict-free
#define KW        128    // W chunk rows resident in smem

// smem per CTA: Ws[128][72] + As[2][128][36] = 73,728 B  (3 CTAs/SM = 221 KB)
#define SMEM_WS_FLOATS (KW * WS_STRIDE)
#define SMEM_AS_FLOATS (2 * 128 * AS_STRIDE)
#define SMEM_GEMM_B    ((SMEM_WS_FLOATS + SMEM_AS_FLOATS) * 4)

// ---------------- scratch (device globals; no allocation allowed) ----------
__device__ float g_x[NN * HID];     // 32 MB
__device__ float g_h[NN * HID];     // 32 MB
__device__ float g_y[NN * HID];     // 32 MB
__device__ int   g_deg[NN];
__device__ float g_dinv[NN];
__device__ int   g_bsum[256];
__device__ int   g_boff[256];
__device__ int   g_off[NN];
__device__ int   g_cur[NN];
__device__ int   g_esrc[NE];
__device__ float g_ecoef[NE];

// cvt.*.tf32.f32 requires a .b32 destination register -> "=r" constraint.
__device__ __forceinline__ uint32_t to_tf32(float x) {
    uint32_t r;
    asm("cvt.rna.tf32.f32 %0, %1;" : "=r"(r) : "f"(x));
    return r;
}
__device__ __forceinline__ float to_tf32f(float x) {
    return __uint_as_float(to_tf32(x));
}
__device__ __forceinline__ uint32_t smem_u32(const void* p) {
    uint32_t a;
    asm("{ .reg .u64 t; cvta.to.shared.u64 t, %1; cvt.u32.u64 %0, t; }"
        : "=r"(a) : "l"(p));
    return a;
}
#define CP_ASYNC16(saddr, gptr) \
    asm volatile("cp.async.cg.shared.global [%0], [%1], 16;" \
                 :: "r"(saddr), "l"(gptr))
#define CP_COMMIT() asm volatile("cp.async.commit_group;" ::: "memory")
#define CP_WAIT0()  asm volatile("cp.async.wait_group 0;" ::: "memory")

// ---------------- degree / CSR build --------------------------------------
__global__ void k_zero_deg() {
    g_deg[blockIdx.x * 256 + threadIdx.x] = 0;
}

__global__ void k_count(const int* __restrict__ edges) {
    int e = blockIdx.x * 256 + threadIdx.x;
    atomicAdd(&g_deg[edges[2 * e + 1]], 1);
}

__global__ void k_dinv() {
    int i = blockIdx.x * 256 + threadIdx.x;
    g_dinv[i] = rsqrtf((float)g_deg[i] + 1.0f);
}

__global__ void k_scan1() {
    __shared__ int s[256];
    int t = threadIdx.x;
    s[t] = g_deg[blockIdx.x * 256 + t];
    __syncthreads();
    for (int o = 128; o > 0; o >>= 1) {
        if (t < o) s[t] += s[t + o];
        __syncthreads();
    }
    if (t == 0) g_bsum[blockIdx.x] = s[0];
}

__global__ void k_scan2() {
    __shared__ int s[256];
    int t = threadIdx.x;
    int v = g_bsum[t];
    s[t] = v;
    __syncthreads();
    for (int o = 1; o < 256; o <<= 1) {
        int u = (t >= o) ? s[t - o] : 0;
        __syncthreads();
        s[t] += u;
        __syncthreads();
    }
    g_boff[t] = s[t] - v;
}

__global__ void k_scan3() {
    __shared__ int s[256];
    int t = threadIdx.x;
    int gi = blockIdx.x * 256 + t;
    int v = g_deg[gi];
    s[t] = v;
    __syncthreads();
    for (int o = 1; o < 256; o <<= 1) {
        int u = (t >= o) ? s[t - o] : 0;
        __syncthreads();
        s[t] += u;
        __syncthreads();
    }
    int excl = s[t] - v + g_boff[blockIdx.x];
    g_off[gi] = excl;
    g_cur[gi] = excl;
}

__global__ void k_fill(const int* __restrict__ edges) {
    int e = blockIdx.x * 256 + threadIdx.x;
    int src = edges[2 * e + 0];
    int dst = edges[2 * e + 1];
    int pos = atomicAdd(&g_cur[dst], 1);
    g_esrc[pos]  = src;
    g_ecoef[pos] = g_dinv[src] * g_dinv[dst];
}

// ---------------- tf32 tensor-core GEMM (legacy mma.sync, sm_80+) ----------
// C[M,128] = (relu? A)[M,K] @ W[K,128] (+bias)
// Block tile 128x64: blockIdx.x = mblk*2 + nblk. 256 threads = 8 warps (4x2);
// warp tile 32x32. K in 128-row W chunks (Ws re-staged per chunk, tf32 RN).
// A staged via cp.async (double-buffered 128x32); relu+tf32 at fragment load.
// 3 CTAs/SM (smem 73.7KB, regs capped 85).
__device__ __forceinline__ void mma_tf32(float* d, uint32_t a0, uint32_t a1,
                                         uint32_t a2, uint32_t a3,
                                         uint32_t b0, uint32_t b1) {
    asm volatile(
        "mma.sync.aligned.m16n8k8.row.col.f32.tf32.tf32.f32 "
        "{%0,%1,%2,%3}, {%4,%5,%6,%7}, {%8,%9}, {%0,%1,%2,%3};"
        : "+f"(d[0]), "+f"(d[1]), "+f"(d[2]), "+f"(d[3])
        : "r"(a0), "r"(a1), "r"(a2), "r"(a3), "r"(b0), "r"(b1));
}

template<int K>
__global__ __launch_bounds__(256, 3)
void k_gemm_mma(const float* __restrict__ A, const float* __restrict__ W,
                const float* __restrict__ bias, float* __restrict__ C,
                int relu_in) {
    extern __shared__ float sm[];
    float* Ws = sm;                        // [KW][WS_STRIDE] (64 cols used)
    float* As = sm + SMEM_WS_FLOATS;       // [2][128][AS_STRIDE]

    int tid  = threadIdx.x;
    int lane = tid & 31, wid = tid >> 5;
    int wr = wid >> 1, wc = wid & 1;       // warp row 0..3, warp col 0..1
    int g = lane >> 2, t = lane & 3;       // fragment coords

    int mblk = blockIdx.x >> 1;
    int nblk = blockIdx.x & 1;

    const float* Ablk = A + (size_t)mblk * 128 * K;
    const float* Wblk = W + nblk * 64;     // col offset into [K][128]

    // this thread's A-chunk slots: 4x 16B covering 128x32 floats
    int arow[4], acol[4];
    uint32_t asaddr[2][4];
    uint32_t as_base = smem_u32(As);
#pragma unroll
    for (int it = 0; it < 4; it++) {
        int u = it * 256 + tid;
        arow[it] = u >> 3;
        acol[it] = (u & 7) * 4;
#pragma unroll
        for (int b = 0; b < 2; b++)
            asaddr[b][it] = as_base +
                (uint32_t)(b * 128 * AS_STRIDE + arow[it] * AS_STRIDE + acol[it]) * 4u;
    }

    float d[2][4][4];
#pragma unroll
    for (int mt = 0; mt < 2; mt++)
#pragma unroll
        for (int nt = 0; nt < 4; nt++)
#pragma unroll
            for (int j = 0; j < 4; j++) d[mt][nt][j] = 0.0f;

    for (int kw = 0; kw < K; kw += KW) {
        __syncthreads();                   // prior chunk's Ws/buffer reads done
        // stage W rows [kw,kw+128) x 64 cols (tf32 RN), float4-vectorized
        for (int u = tid; u < KW * 16; u += 256) {   // 16 float4 per row
            int k = u >> 4, n4 = (u & 15) * 4;
            float4 v = *(const float4*)&Wblk[(size_t)(kw + k) * 128 + n4];
            v.x = to_tf32f(v.x); v.y = to_tf32f(v.y);
            v.z = to_tf32f(v.z); v.w = to_tf32f(v.w);
            *(float4*)&Ws[k * WS_STRIDE + n4] = v;
        }
        // prefetch A chunk 0 of this kw into buffer 0
#pragma unroll
        for (int it = 0; it < 4; it++)
            CP_ASYNC16(asaddr[0][it],
                       &Ablk[(size_t)arow[it] * K + kw + acol[it]]);
        CP_COMMIT();

#pragma unroll
        for (int c = 0; c < 4; c++) {
            int buf = c & 1;
            CP_WAIT0();
            __syncthreads();               // chunk c data + Ws visible; all
                                           // warps past mma(c-1)

            if (c < 3) {                   // issue chunk c+1 during mma of c
                int k0n = kw + (c + 1) * 32;
#pragma unroll
                for (int it = 0; it < 4; it++)
                    CP_ASYNC16(asaddr[buf ^ 1][it],
                               &Ablk[(size_t)arow[it] * K + k0n + acol[it]]);
                CP_COMMIT();
            }

            const float* Ab = As + buf * 128 * AS_STRIDE;
#pragma unroll
            for (int kk = 0; kk < 4; kk++) {
                int kb   = kk * 8;
                int kabs = c * 32 + kb;    // row within this W chunk
                uint32_t b0[4], b1[4];
#pragma unroll
                for (int nt = 0; nt < 4; nt++) {
                    int col = wc * 32 + nt * 8 + g;
                    b0[nt] = __float_as_uint(Ws[(kabs + t)     * WS_STRIDE + col]);
                    b1[nt] = __float_as_uint(Ws[(kabs + t + 4) * WS_STRIDE + col]);
                }
#pragma unroll
                for (int mt = 0; mt < 2; mt++) {
                    int rb = wr * 32 + mt * 16;
                    float f0 = Ab[(rb + g)     * AS_STRIDE + kb + t];
                    float f1 = Ab[(rb + g + 8) * AS_STRIDE + kb + t];
                    float f2 = Ab[(rb + g)     * AS_STRIDE + kb + t + 4];
                    float f3 = Ab[(rb + g + 8) * AS_STRIDE + kb + t + 4];
                    if (relu_in) {
                        f0 = fmaxf(f0, 0.0f); f1 = fmaxf(f1, 0.0f);
                        f2 = fmaxf(f2, 0.0f); f3 = fmaxf(f3, 0.0f);
                    }
                    uint32_t a0 = to_tf32(f0), a1 = to_tf32(f1);
                    uint32_t a2 = to_tf32(f2), a3 = to_tf32(f3);
#pragma unroll
                    for (int nt = 0; nt < 4; nt++)
                        mma_tf32(d[mt][nt], a0, a1, a2, a3, b0[nt], b1[nt]);
                }
            }
            // no trailing sync: next iteration's wait+sync is the guard
        }
    }

    // epilogue: c0,c1 -> (row=g, col=2t,2t+1); c2,c3 -> row=g+8
    int blkrow = mblk * 128;
    int blkcol = nblk * 64;
#pragma unroll
    for (int mt = 0; mt < 2; mt++) {
        int r0 = blkrow + wr * 32 + mt * 16 + g;
#pragma unroll
        for (int nt = 0; nt < 4; nt++) {
            int col = blkcol + wc * 32 + nt * 8 + t * 2;
            float bx = 0.f, by = 0.f;
            if (bias) { bx = bias[col]; by = bias[col + 1]; }
            float2 v0 = make_float2(d[mt][nt][0] + bx, d[mt][nt][1] + by);
            float2 v1 = make_float2(d[mt][nt][2] + bx, d[mt][nt][3] + by);
            *(float2*)&C[(size_t)r0 * 128 + col]       = v0;
            *(float2*)&C[(size_t)(r0 + 8) * 128 + col] = v1;
        }
    }
}

// ---------------- GCN aggregate: warp per node, CSR gather ----------------
__global__ void k_gather(const float* __restrict__ h,
                         const float* __restrict__ bias,
                         float* __restrict__ out) {
    int v    = blockIdx.x * 8 + (threadIdx.x >> 5);
    int lane = threadIdx.x & 31;
    const float4* h4 = (const float4*)h;

    float dv   = g_dinv[v];
    int   base = g_off[v];
    int   cnt  = g_deg[v];

    float4 acc = make_float4(0.f, 0.f, 0.f, 0.f);
#pragma unroll 4
    for (int i = 0; i < cnt; i++) {
        int   s = __ldg(&g_esrc[base + i]);
        float c = __ldg(&g_ecoef[base + i]);
        float4 hs = __ldg(&h4[(size_t)s * 32 + lane]);
        acc.x += hs.x * c; acc.y += hs.y * c;
        acc.z += hs.z * c; acc.w += hs.w * c;
    }
    float  d2 = dv * dv;
    float4 hv = __ldg(&h4[(size_t)v * 32 + lane]);
    float4 b4 = *(const float4*)&bias[lane * 4];
    acc.x += hv.x * d2 + b4.x;
    acc.y += hv.y * d2 + b4.y;
    acc.z += hv.z * d2 + b4.z;
    acc.w += hv.w * d2 + b4.w;
    ((float4*)out)[(size_t)v * 32 + lane] = acc;
}

// ---------------- pooled max + MLP head -----------------------------------
__global__ void k_pool_mlp(const float* __restrict__ X,
                           const float* __restrict__ Wp1,
                           const float* __restrict__ bp1,
                           const float* __restrict__ Wp2,
                           const float* __restrict__ bp2,
                           float* __restrict__ out) {
    __shared__ float p[128];
    __shared__ float red[128];
    int b = blockIdx.x;
    int f = threadIdx.x;

    float m = -3.4e38f;
    const float* base = X + (size_t)b * 256 * 128 + f;
    for (int n = 0; n < 256; n++) m = fmaxf(m, base[n * 128]);
    p[f] = fmaxf(m, 0.0f);
    __syncthreads();

    float acc = bp1[f];
    for (int k = 0; k < 128; k++) acc += p[k] * Wp1[k * 128 + f];
    red[f] = fmaxf(acc, 0.0f) * Wp2[f];
    __syncthreads();
    for (int s = 64; s > 0; s >>= 1) {
        if (f < s) red[f] += red[f + s];
        __syncthreads();
    }
    if (f == 0) out[b] = red[0] + bp2[0];
}

// ---------------- launch ---------------------------------------------------
extern "C" void kernel_launch(void* const* d_in, const int* in_sizes, int n_in,
                              void* d_out, int out_size) {
    const float* adj  = (const float*)d_in[0];
    const int*   edges= (const int*)  d_in[1];
    // d_in[2] = subgraph_idx (contiguous 256-node segments)
    const float* Wdec = (const float*)d_in[3];
    const float* bdec = (const float*)d_in[4];
    const float* Wc1  = (const float*)d_in[5];
    const float* bc1  = (const float*)d_in[6];
    const float* Wc2  = (const float*)d_in[7];
    const float* bc2  = (const float*)d_in[8];
    const float* Wp1  = (const float*)d_in[9];
    const float* bp1  = (const float*)d_in[10];
    const float* Wp2  = (const float*)d_in[11];
    const float* bp2  = (const float*)d_in[12];
    float* out = (float*)d_out;

    float *px, *ph, *py;
    cudaGetSymbolAddress((void**)&px, g_x);
    cudaGetSymbolAddress((void**)&ph, g_h);
    cudaGetSymbolAddress((void**)&py, g_y);

    cudaFuncSetAttribute(k_gemm_mma<KDEC>,
                         cudaFuncAttributeMaxDynamicSharedMemorySize, SMEM_GEMM_B);
    cudaFuncSetAttribute(k_gemm_mma<HID>,
                         cudaFuncAttributeMaxDynamicSharedMemorySize, SMEM_GEMM_B);

    const int GEMM_GRID = (NN / 128) * 2;   // 128x64 tiles

    // CSR head (independent of decode)
    k_zero_deg<<<NN / 256, 256>>>();                                   // 0
    k_count   <<<NE / 256, 256>>>(edges);                              // 1
    k_dinv    <<<NN / 256, 256>>>();                                   // 2

    // decode: x = adj @ Wdec + bdec   (kernel launch index 3 for ncu)
    k_gemm_mma<KDEC><<<GEMM_GRID, 256, SMEM_GEMM_B>>>(adj, Wdec, bdec, px, 0);

    // CSR tail
    k_scan1<<<256, 256>>>();
    k_scan2<<<1, 256>>>();
    k_scan3<<<256, 256>>>();
    k_fill <<<NE / 256, 256>>>(edges);

    // conv1: h = x @ Wc1 ; y = aggregate(h) + h*dinv^2 + bc1
    k_gemm_mma<HID><<<GEMM_GRID, 256, SMEM_GEMM_B>>>(px, Wc1, nullptr, ph, 0);
    k_gather  <<<NN / 8, 256>>>(ph, bc1, py);

    // conv2: h = relu(y) @ Wc2 ; x = aggregate(h) + h*dinv^2 + bc2
    k_gemm_mma<HID><<<GEMM_GRID, 256, SMEM_GEMM_B>>>(py, Wc2, nullptr, ph, 1);
    k_gather  <<<NN / 8, 256>>>(ph, bc2, px);

    // pool (relu∘max) + MLP head
    k_pool_mlp<<<BATCH, 128>>>(px, Wp1, bp1, Wp2, bp2, out);
}

// round 16
// speedup vs baseline: 1.1847x; 1.0631x over previous
#include <cuda_runtime.h>
#include <cuda_bf16.h>
#include <cstdint>

#define NN    65536      // total nodes = B*C*NMAX
#define HID   128
#define NE    1048576    // edges
#define KDEC  256        // NMAX (decode GEMM K)
#define BATCH 256

#define WS_STRIDE 72     // W smem row stride (floats), 72%32=8 -> B-frag conflict-free
#define AS_STRIDE 36     // A smem row stride (floats), 36%32=4 -> A-frag conflict-free
#define KW        128    // W chunk rows resident in smem

// smem per CTA: Ws[128][72] + As[2][128][36] = 73,728 B  (3 CTAs/SM = 221 KB)
#define SMEM_WS_FLOATS (KW * WS_STRIDE)
#define SMEM_AS_FLOATS (2 * 128 * AS_STRIDE)
#define SMEM_GEMM_B    ((SMEM_WS_FLOATS + SMEM_AS_FLOATS) * 4)

// ---------------- scratch (device globals; no allocation allowed) ----------
__device__ float g_x[NN * HID];          // 32 MB (decode out / conv2 in / final x)
__device__ float g_y[NN * HID];          // 32 MB (conv1 aggregate out)
__device__ __nv_bfloat162 g_hb[NN * 64]; // 16 MB (conv GEMM out, bf16; gather in)
__device__ int   g_deg[NN];
__device__ float g_dinv[NN];
__device__ int   g_bsum[256];
__device__ int   g_boff[256];
__device__ int   g_off[NN];
__device__ int   g_cur[NN];
__device__ int   g_esrc[NE];
__device__ float g_ecoef[NE];

// cvt.*.tf32.f32 requires a .b32 destination register -> "=r" constraint.
__device__ __forceinline__ uint32_t to_tf32(float x) {
    uint32_t r;
    asm("cvt.rna.tf32.f32 %0, %1;" : "=r"(r) : "f"(x));
    return r;
}
__device__ __forceinline__ float to_tf32f(float x) {
    return __uint_as_float(to_tf32(x));
}
__device__ __forceinline__ uint32_t smem_u32(const void* p) {
    uint32_t a;
    asm("{ .reg .u64 t; cvta.to.shared.u64 t, %1; cvt.u32.u64 %0, t; }"
        : "=r"(a) : "l"(p));
    return a;
}
#define CP_ASYNC16(saddr, gptr) \
    asm volatile("cp.async.cg.shared.global [%0], [%1], 16;" \
                 :: "r"(saddr), "l"(gptr))
#define CP_COMMIT() asm volatile("cp.async.commit_group;" ::: "memory")
#define CP_WAIT0()  asm volatile("cp.async.wait_group 0;" ::: "memory")

// ---------------- degree / CSR build --------------------------------------
__global__ void k_zero_deg() {
    g_deg[blockIdx.x * 256 + threadIdx.x] = 0;
}

__global__ void k_count(const int* __restrict__ edges) {
    int e = blockIdx.x * 256 + threadIdx.x;
    atomicAdd(&g_deg[edges[2 * e + 1]], 1);
}

__global__ void k_dinv() {
    int i = blockIdx.x * 256 + threadIdx.x;
    g_dinv[i] = rsqrtf((float)g_deg[i] + 1.0f);
}

__global__ void k_scan1() {
    __shared__ int s[256];
    int t = threadIdx.x;
    s[t] = g_deg[blockIdx.x * 256 + t];
    __syncthreads();
    for (int o = 128; o > 0; o >>= 1) {
        if (t < o) s[t] += s[t + o];
        __syncthreads();
    }
    if (t == 0) g_bsum[blockIdx.x] = s[0];
}

__global__ void k_scan2() {
    __shared__ int s[256];
    int t = threadIdx.x;
    int v = g_bsum[t];
    s[t] = v;
    __syncthreads();
    for (int o = 1; o < 256; o <<= 1) {
        int u = (t >= o) ? s[t - o] : 0;
        __syncthreads();
        s[t] += u;
        __syncthreads();
    }
    g_boff[t] = s[t] - v;
}

__global__ void k_scan3() {
    __shared__ int s[256];
    int t = threadIdx.x;
    int gi = blockIdx.x * 256 + t;
    int v = g_deg[gi];
    s[t] = v;
    __syncthreads();
    for (int o = 1; o < 256; o <<= 1) {
        int u = (t >= o) ? s[t - o] : 0;
        __syncthreads();
        s[t] += u;
        __syncthreads();
    }
    int excl = s[t] - v + g_boff[blockIdx.x];
    g_off[gi] = excl;
    g_cur[gi] = excl;
}

__global__ void k_fill(const int* __restrict__ edges) {
    int e = blockIdx.x * 256 + threadIdx.x;
    int src = edges[2 * e + 0];
    int dst = edges[2 * e + 1];
    int pos = atomicAdd(&g_cur[dst], 1);
    g_esrc[pos]  = src;
    g_ecoef[pos] = g_dinv[src] * g_dinv[dst];
}

// ---------------- tf32 tensor-core GEMM (legacy mma.sync, sm_80+) ----------
// C[M,128] = (relu? A)[M,K] @ W[K,128] (+bias)
// Block tile 128x64: blockIdx.x = mblk*2 + nblk. 256 threads = 8 warps (4x2);
// warp tile 32x32. K in 128-row W chunks (Ws re-staged per chunk, tf32 RN).
// A staged via cp.async (double-buffered 128x32); relu+tf32 at fragment load.
// 3 CTAs/SM. BF16OUT: output written as bf16 pairs (replaces fp32 output).
__device__ __forceinline__ void mma_tf32(float* d, uint32_t a0, uint32_t a1,
                                         uint32_t a2, uint32_t a3,
                                         uint32_t b0, uint32_t b1) {
    asm volatile(
        "mma.sync.aligned.m16n8k8.row.col.f32.tf32.tf32.f32 "
        "{%0,%1,%2,%3}, {%4,%5,%6,%7}, {%8,%9}, {%0,%1,%2,%3};"
        : "+f"(d[0]), "+f"(d[1]), "+f"(d[2]), "+f"(d[3])
        : "r"(a0), "r"(a1), "r"(a2), "r"(a3), "r"(b0), "r"(b1));
}

template<int K, bool BF16OUT>
__global__ __launch_bounds__(256, 3)
void k_gemm_mma(const float* __restrict__ A, const float* __restrict__ W,
                const float* __restrict__ bias, void* __restrict__ Cout,
                int relu_in) {
    extern __shared__ float sm[];
    float* Ws = sm;                        // [KW][WS_STRIDE] (64 cols used)
    float* As = sm + SMEM_WS_FLOATS;       // [2][128][AS_STRIDE]

    int tid  = threadIdx.x;
    int lane = tid & 31, wid = tid >> 5;
    int wr = wid >> 1, wc = wid & 1;       // warp row 0..3, warp col 0..1
    int g = lane >> 2, t = lane & 3;       // fragment coords

    int mblk = blockIdx.x >> 1;
    int nblk = blockIdx.x & 1;

    const float* Ablk = A + (size_t)mblk * 128 * K;
    const float* Wblk = W + nblk * 64;     // col offset into [K][128]

    // this thread's A-chunk slots: 4x 16B covering 128x32 floats
    int arow[4], acol[4];
    uint32_t asaddr[2][4];
    uint32_t as_base = smem_u32(As);
#pragma unroll
    for (int it = 0; it < 4; it++) {
        int u = it * 256 + tid;
        arow[it] = u >> 3;
        acol[it] = (u & 7) * 4;
#pragma unroll
        for (int b = 0; b < 2; b++)
            asaddr[b][it] = as_base +
                (uint32_t)(b * 128 * AS_STRIDE + arow[it] * AS_STRIDE + acol[it]) * 4u;
    }

    float d[2][4][4];
#pragma unroll
    for (int mt = 0; mt < 2; mt++)
#pragma unroll
        for (int nt = 0; nt < 4; nt++)
#pragma unroll
            for (int j = 0; j < 4; j++) d[mt][nt][j] = 0.0f;

    for (int kw = 0; kw < K; kw += KW) {
        __syncthreads();                   // prior chunk's Ws/buffer reads done
        // stage W rows [kw,kw+128) x 64 cols (tf32 RN), float4-vectorized
        for (int u = tid; u < KW * 16; u += 256) {   // 16 float4 per row
            int k = u >> 4, n4 = (u & 15) * 4;
            float4 v = *(const float4*)&Wblk[(size_t)(kw + k) * 128 + n4];
            v.x = to_tf32f(v.x); v.y = to_tf32f(v.y);
            v.z = to_tf32f(v.z); v.w = to_tf32f(v.w);
            *(float4*)&Ws[k * WS_STRIDE + n4] = v;
        }
        // prefetch A chunk 0 of this kw into buffer 0
#pragma unroll
        for (int it = 0; it < 4; it++)
            CP_ASYNC16(asaddr[0][it],
                       &Ablk[(size_t)arow[it] * K + kw + acol[it]]);
        CP_COMMIT();

#pragma unroll
        for (int c = 0; c < 4; c++) {
            int buf = c & 1;
            CP_WAIT0();
            __syncthreads();               // chunk c data + Ws visible; all
                                           // warps past mma(c-1)

            if (c < 3) {                   // issue chunk c+1 during mma of c
                int k0n = kw + (c + 1) * 32;
#pragma unroll
                for (int it = 0; it < 4; it++)
                    CP_ASYNC16(asaddr[buf ^ 1][it],
                               &Ablk[(size_t)arow[it] * K + k0n + acol[it]]);
                CP_COMMIT();
            }

            const float* Ab = As + buf * 128 * AS_STRIDE;
#pragma unroll
            for (int kk = 0; kk < 4; kk++) {
                int kb   = kk * 8;
                int kabs = c * 32 + kb;    // row within this W chunk
                uint32_t b0[4], b1[4];
#pragma unroll
                for (int nt = 0; nt < 4; nt++) {
                    int col = wc * 32 + nt * 8 + g;
                    b0[nt] = __float_as_uint(Ws[(kabs + t)     * WS_STRIDE + col]);
                    b1[nt] = __float_as_uint(Ws[(kabs + t + 4) * WS_STRIDE + col]);
                }
#pragma unroll
                for (int mt = 0; mt < 2; mt++) {
                    int rb = wr * 32 + mt * 16;
                    float f0 = Ab[(rb + g)     * AS_STRIDE + kb + t];
                    float f1 = Ab[(rb + g + 8) * AS_STRIDE + kb + t];
                    float f2 = Ab[(rb + g)     * AS_STRIDE + kb + t + 4];
                    float f3 = Ab[(rb + g + 8) * AS_STRIDE + kb + t + 4];
                    if (relu_in) {
                        f0 = fmaxf(f0, 0.0f); f1 = fmaxf(f1, 0.0f);
                        f2 = fmaxf(f2, 0.0f); f3 = fmaxf(f3, 0.0f);
                    }
                    uint32_t a0 = to_tf32(f0), a1 = to_tf32(f1);
                    uint32_t a2 = to_tf32(f2), a3 = to_tf32(f3);
#pragma unroll
                    for (int nt = 0; nt < 4; nt++)
                        mma_tf32(d[mt][nt], a0, a1, a2, a3, b0[nt], b1[nt]);
                }
            }
            // no trailing sync: next iteration's wait+sync is the guard
        }
    }

    // epilogue: c0,c1 -> (row=g, col=2t,2t+1); c2,c3 -> row=g+8
    int blkrow = mblk * 128;
    int blkcol = nblk * 64;
#pragma unroll
    for (int mt = 0; mt < 2; mt++) {
        int r0 = blkrow + wr * 32 + mt * 16 + g;
#pragma unroll
        for (int nt = 0; nt < 4; nt++) {
            int col = blkcol + wc * 32 + nt * 8 + t * 2;
            float bx = 0.f, by = 0.f;
            if (bias) { bx = bias[col]; by = bias[col + 1]; }
            float2 v0 = make_float2(d[mt][nt][0] + bx, d[mt][nt][1] + by);
            float2 v1 = make_float2(d[mt][nt][2] + bx, d[mt][nt][3] + by);
            if (BF16OUT) {
                __nv_bfloat162* Cb = (__nv_bfloat162*)Cout;
                Cb[(size_t)r0 * 64 + (col >> 1)] =
                    __floats2bfloat162_rn(v0.x, v0.y);
                Cb[(size_t)(r0 + 8) * 64 + (col >> 1)] =
                    __floats2bfloat162_rn(v1.x, v1.y);
            } else {
                float* C = (float*)Cout;
                *(float2*)&C[(size_t)r0 * 128 + col]       = v0;
                *(float2*)&C[(size_t)(r0 + 8) * 128 + col] = v1;
            }
        }
    }
}

// ---------------- GCN aggregate: warp per node, CSR gather (bf16 h) -------
// out[v] = sum coef[e]*hb[src[e]] + hb[v]*dinv^2 + bias   (fp32 accumulate)
__global__ void k_gather(const __nv_bfloat162* __restrict__ hb,
                         const float* __restrict__ bias,
                         float* __restrict__ out) {
    int v    = blockIdx.x * 8 + (threadIdx.x >> 5);
    int lane = threadIdx.x & 31;
    const uint2* hb2 = (const uint2*)hb;   // 8B = 4 bf16 features per lane

    float dv   = g_dinv[v];
    int   base = g_off[v];
    int   cnt  = g_deg[v];

    float4 acc = make_float4(0.f, 0.f, 0.f, 0.f);
#pragma unroll 4
    for (int i = 0; i < cnt; i++) {
        int   s = __ldg(&g_esrc[base + i]);
        float c = __ldg(&g_ecoef[base + i]);
        uint2 raw = __ldg(&hb2[(size_t)s * 32 + lane]);
        float2 f0 = __bfloat1622float2(*reinterpret_cast<const __nv_bfloat162*>(&raw.x));
        float2 f1 = __bfloat1622float2(*reinterpret_cast<const __nv_bfloat162*>(&raw.y));
        acc.x += f0.x * c; acc.y += f0.y * c;
        acc.z += f1.x * c; acc.w += f1.y * c;
    }
    float d2 = dv * dv;
    uint2 rawv = __ldg(&hb2[(size_t)v * 32 + lane]);
    float2 h0 = __bfloat1622float2(*reinterpret_cast<const __nv_bfloat162*>(&rawv.x));
    float2 h1 = __bfloat1622float2(*reinterpret_cast<const __nv_bfloat162*>(&rawv.y));
    float4 b4 = *(const float4*)&bias[lane * 4];
    acc.x += h0.x * d2 + b4.x;
    acc.y += h0.y * d2 + b4.y;
    acc.z += h1.x * d2 + b4.z;
    acc.w += h1.y * d2 + b4.w;
    ((float4*)out)[(size_t)v * 32 + lane] = acc;
}

// ---------------- pooled max + MLP head -----------------------------------
__global__ void k_pool_mlp(const float* __restrict__ X,
                           const float* __restrict__ Wp1,
                           const float* __restrict__ bp1,
                           const float* __restrict__ Wp2,
                           const float* __restrict__ bp2,
                           float* __restrict__ out) {
    __shared__ float p[128];
    __shared__ float red[128];
    int b = blockIdx.x;
    int f = threadIdx.x;

    float m = -3.4e38f;
    const float* base = X + (size_t)b * 256 * 128 + f;
    for (int n = 0; n < 256; n++) m = fmaxf(m, base[n * 128]);
    p[f] = fmaxf(m, 0.0f);
    __syncthreads();

    float acc = bp1[f];
    for (int k = 0; k < 128; k++) acc += p[k] * Wp1[k * 128 + f];
    red[f] = fmaxf(acc, 0.0f) * Wp2[f];
    __syncthreads();
    for (int s = 64; s > 0; s >>= 1) {
        if (f < s) red[f] += red[f + s];
        __syncthreads();
    }
    if (f == 0) out[b] = red[0] + bp2[0];
}

// ---------------- launch ---------------------------------------------------
extern "C" void kernel_launch(void* const* d_in, const int* in_sizes, int n_in,
                              void* d_out, int out_size) {
    const float* adj  = (const float*)d_in[0];
    const int*   edges= (const int*)  d_in[1];
    // d_in[2] = subgraph_idx (contiguous 256-node segments)
    const float* Wdec = (const float*)d_in[3];
    const float* bdec = (const float*)d_in[4];
    const float* Wc1  = (const float*)d_in[5];
    const float* bc1  = (const float*)d_in[6];
    const float* Wc2  = (const float*)d_in[7];
    const float* bc2  = (const float*)d_in[8];
    const float* Wp1  = (const float*)d_in[9];
    const float* bp1  = (const float*)d_in[10];
    const float* Wp2  = (const float*)d_in[11];
    const float* bp2  = (const float*)d_in[12];
    float* out = (float*)d_out;

    float *px, *py;
    __nv_bfloat162* phb;
    cudaGetSymbolAddress((void**)&px,  g_x);
    cudaGetSymbolAddress((void**)&py,  g_y);
    cudaGetSymbolAddress((void**)&phb, g_hb);

    cudaFuncSetAttribute(k_gemm_mma<KDEC, false>,
                         cudaFuncAttributeMaxDynamicSharedMemorySize, SMEM_GEMM_B);
    cudaFuncSetAttribute(k_gemm_mma<HID, true>,
                         cudaFuncAttributeMaxDynamicSharedMemorySize, SMEM_GEMM_B);

    const int GEMM_GRID = (NN / 128) * 2;   // 128x64 tiles

    // CSR head (independent of decode)
    k_zero_deg<<<NN / 256, 256>>>();                                   // 0
    k_count   <<<NE / 256, 256>>>(edges);                              // 1
    k_dinv    <<<NN / 256, 256>>>();                                   // 2

    // decode: x = adj @ Wdec + bdec   (kernel launch index 3 for ncu)
    k_gemm_mma<KDEC, false><<<GEMM_GRID, 256, SMEM_GEMM_B>>>(adj, Wdec, bdec,
                                                             px, 0);

    // CSR tail
    k_scan1<<<256, 256>>>();
    k_scan2<<<1, 256>>>();
    k_scan3<<<256, 256>>>();
    k_fill <<<NE / 256, 256>>>(edges);

    // conv1: hb = x @ Wc1 (bf16) ; y = agg(hb) + hb*dinv^2 + bc1 (fp32)
    k_gemm_mma<HID, true><<<GEMM_GRID, 256, SMEM_GEMM_B>>>(px, Wc1, nullptr,
                                                           phb, 0);
    k_gather<<<NN / 8, 256>>>(phb, bc1, py);

    // conv2: hb = relu(y) @ Wc2 (bf16) ; x = agg(hb) + hb*dinv^2 + bc2 (fp32)
    k_gemm_mma<HID, true><<<GEMM_GRID, 256, SMEM_GEMM_B>>>(py, Wc2, nullptr,
                                                           phb, 1);
    k_gather<<<NN / 8, 256>>>(phb, bc2, px);

    // pool (relu∘max) + MLP head
    k_pool_mlp<<<BATCH, 128>>>(px, Wp1, bp1, Wp2, bp2, out);
}